// round 2
// baseline (speedup 1.0000x reference)
#include <cuda_runtime.h>
#include <cuda_bf16.h>
#include <cstdint>
#include <cstddef>

// ============================================================================
// KMeansLoss on GB300 via legacy mma.sync (HMMA) — the harness ptxas target is
// sm_103 (no 'a'), so tcgen05/TMEM are unavailable. Uses sm_80-era PTX only.
//
// loss = ALPHA * mean_n sqrt(max( xsq[n] + min_k( csq[k] - 2*dot(x_n,c_k) ), 0))
//
// Kernel 0: convert centers fp32 -> bf16 in mma-fragment order (global, 256KB)
//           + exact fp32 csq[k].
// Kernel 1: 512 CTAs x 128 thr. Each warp owns 32 rows (2 m16 tiles), A kept
//           in 128 regs (fragment order, staged once through smem, fusing
//           exact fp32 xsq). Loop 16 N-chunks of 32 centers: cp.async double-
//           buffered B, 128 HMMA/warp/chunk, fold (csq - 2*dot) into running
//           per-row min. Deterministic partial sum per CTA.
// Kernel 2: deterministic reduction of 512 partials -> scalar.
// ============================================================================

namespace km {

constexpr int BATCH = 65536;
constexpr int KC    = 512;
constexpr int DIM   = 256;
constexpr float ALPHA = 0.05f;

constexpr int M_CTA    = 128;
constexpr int NUM_CTAS = BATCH / M_CTA;     // 512
constexpr int NCH      = 32;                // centers per chunk
constexpr int NCHUNKS  = KC / NCH;          // 16
constexpr int CHUNK_BYTES = NCH * DIM * 2;  // 16384

// ---- dynamic smem layout ----
constexpr int SM_CSQ = 0;                   // 512 f
constexpr int SM_XSQ = 2048;                // 128 f
constexpr int SM_RED = 2560;                // 4 f
constexpr int SM_AST = 4096;                // 64 KB A fragment staging
constexpr int SM_BB  = 4096 + 65536;        // 2 x 16 KB B buffers
constexpr int SMEM_TOTAL = SM_BB + 2 * CHUNK_BYTES;   // 102400

// B fragments: [nbg(64)][ks(16)][lane(32)] x uint2  (b0 = k pair, b1 = k+8 pair)
__device__ uint2 g_Bfrag[(KC / 8) * 16 * 32];
__device__ float g_csq[KC];
__device__ float g_partials[NUM_CTAS];

// ---------------------------- helpers ---------------------------------------
__device__ __forceinline__ uint32_t pk_bf16x2(float lo, float hi) {
    uint32_t r;
    asm("cvt.rn.bf16x2.f32 %0, %1, %2;" : "=r"(r) : "f"(hi), "f"(lo));
    return r;
}

__device__ __forceinline__ void mma16816(float c[4], const uint32_t a[4],
                                         uint32_t b0, uint32_t b1) {
    asm volatile(
        "mma.sync.aligned.m16n8k16.row.col.f32.bf16.bf16.f32 "
        "{%0,%1,%2,%3}, {%4,%5,%6,%7}, {%8,%9}, {%0,%1,%2,%3};"
        : "+f"(c[0]), "+f"(c[1]), "+f"(c[2]), "+f"(c[3])
        : "r"(a[0]), "r"(a[1]), "r"(a[2]), "r"(a[3]), "r"(b0), "r"(b1));
}

__device__ __forceinline__ uint32_t smem_u32(const void* p) {
    return (uint32_t)__cvta_generic_to_shared(p);
}
__device__ __forceinline__ void cp16(uint32_t sdst, const void* gsrc) {
    asm volatile("cp.async.cg.shared.global [%0], [%1], 16;"
                 :: "r"(sdst), "l"(gsrc) : "memory");
}
__device__ __forceinline__ void cp_commit() {
    asm volatile("cp.async.commit_group;" ::: "memory");
}
template <int N>
__device__ __forceinline__ void cp_wait() {
    asm volatile("cp.async.wait_group %0;" :: "n"(N) : "memory");
}

// ------------------------- kernel 0: center convert -------------------------
// grid 8 x 256: warp handles one 8-center block (nbg), emits fragment-order bf16.
__global__ void __launch_bounds__(256) convert_centers(const float* __restrict__ ctr) {
    const int tid = threadIdx.x;
    const int w   = tid >> 5;
    const int l   = tid & 31;
    const int nbg = blockIdx.x * 8 + w;         // 0..63
    const int n   = nbg * 8 + (l >> 2);         // center index
    const float* row = ctr + (size_t)n * DIM;

    float cs = 0.0f;
    #pragma unroll
    for (int ks = 0; ks < 16; ++ks) {
        const int k0 = ks * 16 + 2 * (l & 3);
        const float2 v0 = *reinterpret_cast<const float2*>(row + k0);
        const float2 v1 = *reinterpret_cast<const float2*>(row + k0 + 8);
        cs = fmaf(v0.x, v0.x, cs); cs = fmaf(v0.y, v0.y, cs);
        cs = fmaf(v1.x, v1.x, cs); cs = fmaf(v1.y, v1.y, cs);
        uint2 u;
        u.x = pk_bf16x2(v0.x, v0.y);
        u.y = pk_bf16x2(v1.x, v1.y);
        g_Bfrag[(nbg * 16 + ks) * 32 + l] = u;
    }
    cs += __shfl_xor_sync(0xFFFFFFFFu, cs, 1);
    cs += __shfl_xor_sync(0xFFFFFFFFu, cs, 2);
    if ((l & 3) == 0) g_csq[n] = cs;
}

// ------------------------- kernel 1: main GEMM+min --------------------------
__global__ void __launch_bounds__(128, 2)
kmeans_main(const float* __restrict__ emb) {
    extern __shared__ char smem[];
    const int tid = threadIdx.x;
    const int w   = tid >> 5;        // warp 0..3
    const int l   = tid & 31;
    const int m0  = blockIdx.x * M_CTA;
    float* csq_s = reinterpret_cast<float*>(smem + SM_CSQ);
    float* xsq_s = reinterpret_cast<float*>(smem + SM_XSQ);
    float* red_s = reinterpret_cast<float*>(smem + SM_RED);
    const uint32_t sbase = smem_u32(smem);

    // csq -> smem (512 floats)
    reinterpret_cast<float4*>(csq_s)[tid] = reinterpret_cast<const float4*>(g_csq)[tid];

    // prefetch B chunk 0
    {
        const char* src = reinterpret_cast<const char*>(g_Bfrag);
        #pragma unroll
        for (int i = 0; i < 8; ++i) {
            const int off = (i * 128 + tid) * 16;
            cp16(sbase + SM_BB + off, src + off);
        }
        cp_commit();
    }

    // ---- A: gmem fp32 -> bf16 fragment staging in smem, fused exact xsq ----
    // warp w owns rows [w*32, w*32+32). Pass 'it' covers 8 rows.
    #pragma unroll
    for (int it = 0; it < 4; ++it) {
        const int row = w * 32 + it * 8 + (l >> 2);
        const int mt  = it >> 1;
        const int slotoff = ((it & 1) + 2 * ((l >> 1) & 1)) * 4;
        const int lane0   = (l >> 2) * 4 + 2 * (l & 1);
        const float4* src = reinterpret_cast<const float4*>(
            emb + (size_t)(m0 + row) * DIM) + (l & 3);
        char* abase = smem + SM_AST + ((w * 2 + mt) * 16) * 32 * 16;
        float xs = 0.0f;
        #pragma unroll
        for (int i = 0; i < 16; ++i) {
            const float4 v = src[i * 4];
            xs = fmaf(v.x, v.x, xs); xs = fmaf(v.y, v.y, xs);
            xs = fmaf(v.z, v.z, xs); xs = fmaf(v.w, v.w, xs);
            const uint32_t u0 = pk_bf16x2(v.x, v.y);
            const uint32_t u1 = pk_bf16x2(v.z, v.w);
            char* ad = abase + (i * 32 + lane0) * 16 + slotoff;
            *reinterpret_cast<uint32_t*>(ad)      = u0;
            *reinterpret_cast<uint32_t*>(ad + 16) = u1;   // lane0+1
        }
        xs += __shfl_xor_sync(0xFFFFFFFFu, xs, 1);
        xs += __shfl_xor_sync(0xFFFFFFFFu, xs, 2);
        if ((l & 3) == 0) xsq_s[row] = xs;
    }
    __syncwarp();

    // ---- A fragments smem -> regs: a[mt][ks][0..3] ----
    uint32_t a[2][16][4];
    #pragma unroll
    for (int mt = 0; mt < 2; ++mt) {
        #pragma unroll
        for (int ks = 0; ks < 16; ++ks) {
            const uint4 q = *reinterpret_cast<const uint4*>(
                smem + SM_AST + (((w * 2 + mt) * 16 + ks) * 32 + l) * 16);
            a[mt][ks][0] = q.x; a[mt][ks][1] = q.y;
            a[mt][ks][2] = q.z; a[mt][ks][3] = q.w;
        }
    }

    float minv[2][2];
    minv[0][0] = 3.4e38f; minv[0][1] = 3.4e38f;
    minv[1][0] = 3.4e38f; minv[1][1] = 3.4e38f;

    #pragma unroll 1
    for (int ck = 0; ck < NCHUNKS; ++ck) {
        if (ck + 1 < NCHUNKS) {
            const char* src = reinterpret_cast<const char*>(g_Bfrag)
                              + (ck + 1) * CHUNK_BYTES;
            const uint32_t dst = sbase + SM_BB + ((ck + 1) & 1) * CHUNK_BYTES;
            #pragma unroll
            for (int i = 0; i < 8; ++i) {
                const int off = (i * 128 + tid) * 16;
                cp16(dst + off, src + off);
            }
            cp_commit();
            cp_wait<1>();
        } else {
            cp_wait<0>();
        }
        __syncthreads();

        float acc[2][4][4];
        #pragma unroll
        for (int mt = 0; mt < 2; ++mt)
            #pragma unroll
            for (int nb = 0; nb < 4; ++nb)
                #pragma unroll
                for (int c = 0; c < 4; ++c) acc[mt][nb][c] = 0.0f;

        const char* bb = smem + SM_BB + (ck & 1) * CHUNK_BYTES;
        #pragma unroll
        for (int ks = 0; ks < 16; ++ks) {
            #pragma unroll
            for (int nb = 0; nb < 4; ++nb) {
                const uint2 b = *reinterpret_cast<const uint2*>(
                    bb + ((nb * 16 + ks) * 32 + l) * 8);
                mma16816(acc[0][nb], a[0][ks], b.x, b.y);
                mma16816(acc[1][nb], a[1][ks], b.x, b.y);
            }
        }

        // fold (csq - 2*dot) into running min
        #pragma unroll
        for (int nb = 0; nb < 4; ++nb) {
            const int col = ck * NCH + nb * 8 + 2 * (l & 3);
            const float cq0 = csq_s[col];
            const float cq1 = csq_s[col + 1];
            #pragma unroll
            for (int mt = 0; mt < 2; ++mt) {
                const float v0 = fminf(fmaf(-2.0f, acc[mt][nb][0], cq0),
                                       fmaf(-2.0f, acc[mt][nb][1], cq1));
                const float v1 = fminf(fmaf(-2.0f, acc[mt][nb][2], cq0),
                                       fmaf(-2.0f, acc[mt][nb][3], cq1));
                minv[mt][0] = fminf(minv[mt][0], v0);
                minv[mt][1] = fminf(minv[mt][1], v1);
            }
        }
        __syncthreads();   // all warps done with buf (ck&1) before it is refilled
    }

    // ---- epilogue: per-row min -> sqrt -> deterministic partial sum ----
    float s = 0.0f;
    #pragma unroll
    for (int mt = 0; mt < 2; ++mt) {
        #pragma unroll
        for (int h = 0; h < 2; ++h) {
            float m = minv[mt][h];
            m = fminf(m, __shfl_xor_sync(0xFFFFFFFFu, m, 1));
            m = fminf(m, __shfl_xor_sync(0xFFFFFFFFu, m, 2));
            const int r = w * 32 + mt * 16 + h * 8 + (l >> 2);
            const float d = sqrtf(fmaxf(xsq_s[r] + m, 0.0f));
            if ((l & 3) == 0) s += d;
        }
    }
    #pragma unroll
    for (int off = 16; off; off >>= 1) s += __shfl_down_sync(0xFFFFFFFFu, s, off);
    if (l == 0) red_s[w] = s;
    __syncthreads();
    if (tid == 0)
        g_partials[blockIdx.x] = (red_s[0] + red_s[1]) + (red_s[2] + red_s[3]);
}

// ------------------------- kernel 2: finalize --------------------------------
__global__ void __launch_bounds__(512) kmeans_finalize(float* __restrict__ out) {
    __shared__ float sm[16];
    const int tid = threadIdx.x;                // 512 threads
    float v = g_partials[tid];
    #pragma unroll
    for (int off = 16; off; off >>= 1) v += __shfl_down_sync(0xFFFFFFFFu, v, off);
    if ((tid & 31) == 0) sm[tid >> 5] = v;
    __syncthreads();
    if (tid == 0) {
        float t = 0.0f;
        #pragma unroll
        for (int i = 0; i < 16; ++i) t += sm[i];
        out[0] = t * (ALPHA / (float)BATCH);
    }
}

} // namespace km

extern "C" void kernel_launch(void* const* d_in, const int* in_sizes, int n_in,
                              void* d_out, int out_size) {
    const float* emb = (const float*)d_in[0];   // [65536, 256] fp32
    const float* ctr = (const float*)d_in[1];   // [512, 256]  fp32
    float* out = (float*)d_out;                 // scalar fp32

    cudaFuncSetAttribute(km::kmeans_main,
                         cudaFuncAttributeMaxDynamicSharedMemorySize, km::SMEM_TOTAL);

    km::convert_centers<<<8, 256>>>(ctr);
    km::kmeans_main<<<km::NUM_CTAS, 128, km::SMEM_TOTAL>>>(emb);
    km::kmeans_finalize<<<1, 512>>>(out);
}